// round 2
// baseline (speedup 1.0000x reference)
#include <cuda_runtime.h>
#include <cstdint>
#include <math.h>

// Problem constants (from reference)
#define MAXN 100000
#define D0 128
#define DL 64

// Scratch (static __device__ arrays: allowed; no runtime allocation)
__device__ float g_h[MAXN * D0];    // encoder out / later hw1 [N,64]
__device__ float g_hw[MAXN * D0];   // hw0 [N,128] / later agg1 [N,64]
__device__ float g_agg[MAXN * D0];  // agg0 -> h1 [N,128] / later h2 [N,64]
__device__ float g_dinv[MAXN];
__device__ int   g_deg[MAXN];
__device__ float g_p[MAXN];
__device__ float g_q[MAXN];

// ---------------- degree ----------------
__global__ void k_zero_deg(int n) {
    int i = blockIdx.x * blockDim.x + threadIdx.x;
    if (i < n) g_deg[i] = 0;
}

__global__ void k_count_deg(const int* __restrict__ ei, int E) {
    int e = blockIdx.x * blockDim.x + threadIdx.x;
    if (e >= E) return;
    int d = ei[E + e];
    atomicAdd(&g_deg[d], 1);
}

__global__ void k_dinv(int n) {
    int i = blockIdx.x * blockDim.x + threadIdx.x;
    if (i < n) g_dinv[i] = rsqrtf((float)(g_deg[i] + 1));  // +1 self-loop
}

// ---------------- encoder: h = relu(x[N,16] @ W[16,128] + b) ----------------
__global__ void k_encoder(const float* __restrict__ x, const float* __restrict__ W,
                          const float* __restrict__ b, float* __restrict__ h, int nRows) {
    __shared__ float Ws[16 * 128];
    __shared__ float bs[128];
    __shared__ float xs[16][16];
    int t = threadIdx.x;
    for (int i = t; i < 16 * 128; i += 256) Ws[i] = W[i];
    if (t < 128) bs[t] = b[t];
    int rowBase = blockIdx.x * 16;
    {
        int r = t / 16, k = t % 16;
        int gr = rowBase + r;
        xs[r][k] = (gr < nRows) ? x[(size_t)gr * 16 + k] : 0.f;
    }
    __syncthreads();
    int col = t & 127;
    int r0 = (t >> 7) * 8;
#pragma unroll
    for (int r = r0; r < r0 + 8; ++r) {
        float acc = bs[col];
#pragma unroll
        for (int k = 0; k < 16; ++k) acc += xs[r][k] * Ws[k * 128 + col];
        int gr = rowBase + r;
        if (gr < nRows) h[(size_t)gr * 128 + col] = fmaxf(acc, 0.f);
    }
}

// ---------------- SGEMM: C[N,BN] = A[N,128] @ W[128,BN] ----------------
template <int BN, int TN>
__global__ void k_sgemm(const float* __restrict__ A, const float* __restrict__ W,
                        float* __restrict__ C, int nRows) {
    constexpr int BM = 128, BK = 16, TM = 8;
    constexpr int THREADS = (BM / TM) * (BN / TN);  // 256
    __shared__ float As[BK][BM];
    __shared__ float Bs[BK][BN];
    int tid = threadIdx.x;
    int trow = tid / (BN / TN);
    int tcol = tid % (BN / TN);
    int rowBase = blockIdx.x * BM;
    float acc[TM][TN];
#pragma unroll
    for (int i = 0; i < TM; ++i)
#pragma unroll
        for (int j = 0; j < TN; ++j) acc[i][j] = 0.f;

    for (int k0 = 0; k0 < 128; k0 += BK) {
        // load A tile (BM x BK), transposed into As[k][row]
#pragma unroll
        for (int i = 0; i < (BM * BK) / (THREADS * 4); ++i) {
            int idx = tid + i * THREADS;        // float4 slot
            int r = idx / (BK / 4);
            int kk = (idx % (BK / 4)) * 4;
            float4 v = make_float4(0.f, 0.f, 0.f, 0.f);
            int gr = rowBase + r;
            if (gr < nRows) v = *(const float4*)(A + (size_t)gr * 128 + k0 + kk);
            As[kk + 0][r] = v.x; As[kk + 1][r] = v.y;
            As[kk + 2][r] = v.z; As[kk + 3][r] = v.w;
        }
        // load B tile (BK x BN)
#pragma unroll
        for (int i = 0; i < (BK * BN) / (THREADS * 4); ++i) {
            int idx = tid + i * THREADS;
            int kk = idx / (BN / 4);
            int c = (idx % (BN / 4)) * 4;
            *(float4*)&Bs[kk][c] = *(const float4*)(W + (size_t)(k0 + kk) * BN + c);
        }
        __syncthreads();
#pragma unroll
        for (int k = 0; k < BK; ++k) {
            float ra[TM], rb[TN];
#pragma unroll
            for (int i = 0; i < TM; ++i) ra[i] = As[k][trow * TM + i];
#pragma unroll
            for (int j = 0; j < TN; ++j) rb[j] = Bs[k][tcol * TN + j];
#pragma unroll
            for (int i = 0; i < TM; ++i)
#pragma unroll
                for (int j = 0; j < TN; ++j) acc[i][j] += ra[i] * rb[j];
        }
        __syncthreads();
    }
#pragma unroll
    for (int i = 0; i < TM; ++i) {
        int gr = rowBase + trow * TM + i;
        if (gr < nRows) {
#pragma unroll
            for (int j = 0; j < TN; j += 4) {
                *(float4*)(C + (size_t)gr * BN + tcol * TN + j) =
                    make_float4(acc[i][j], acc[i][j + 1], acc[i][j + 2], acc[i][j + 3]);
            }
        }
    }
}

// ---------------- agg init with self-loop term: agg[i,:] = hw[i,:] * dinv[i]^2 ----------------
__global__ void k_init_self(const float* __restrict__ hw, float* __restrict__ agg,
                            int total, int D) {
    int i = blockIdx.x * blockDim.x + threadIdx.x;  // float4 index
    if (i * 4 >= total) return;
    int row = (i * 4) / D;
    float s = g_dinv[row];
    s = s * s;
    float4 v = ((const float4*)hw)[i];
    v.x *= s; v.y *= s; v.z *= s; v.w *= s;
    ((float4*)agg)[i] = v;
}

// ---------------- scatter: agg[dst,:] += hw[src,:] * dinv[src]*dinv[dst] ----------------
__global__ void k_scatter128(const int* __restrict__ ei, int E,
                             const float* __restrict__ hw, float* __restrict__ agg) {
    int e = blockIdx.x * (blockDim.x >> 5) + (threadIdx.x >> 5);
    if (e >= E) return;
    int lane = threadIdx.x & 31;
    int s = ei[e];
    int d = ei[E + e];
    float nrm = g_dinv[s] * g_dinv[d];
    float4 v = ((const float4*)(hw + (size_t)s * 128))[lane];
    v.x *= nrm; v.y *= nrm; v.z *= nrm; v.w *= nrm;
    float* p = agg + (size_t)d * 128 + lane * 4;
    asm volatile("red.global.add.v4.f32 [%0], {%1,%2,%3,%4};"
                 :: "l"(p), "f"(v.x), "f"(v.y), "f"(v.z), "f"(v.w) : "memory");
}

__global__ void k_scatter64(const int* __restrict__ ei, int E,
                            const float* __restrict__ hw, float* __restrict__ agg) {
    int e = blockIdx.x * (blockDim.x >> 4) + (threadIdx.x >> 4);
    if (e >= E) return;
    int l = threadIdx.x & 15;
    int s = ei[e];
    int d = ei[E + e];
    float nrm = g_dinv[s] * g_dinv[d];
    float4 v = ((const float4*)(hw + (size_t)s * 64))[l];
    v.x *= nrm; v.y *= nrm; v.z *= nrm; v.w *= nrm;
    float* p = agg + (size_t)d * 64 + l * 4;
    asm volatile("red.global.add.v4.f32 [%0], {%1,%2,%3,%4};"
                 :: "l"(p), "f"(v.x), "f"(v.y), "f"(v.z), "f"(v.w) : "memory");
}

// ---------------- finalize: out = relu(in + b) ----------------
__global__ void k_finalize(const float* __restrict__ in, const float* __restrict__ b,
                           float* __restrict__ out, int total, int D) {
    int i = blockIdx.x * blockDim.x + threadIdx.x;  // float4 index
    if (i * 4 >= total) return;
    int col = (i * 4) % D;
    float4 v = ((const float4*)in)[i];
    v.x = fmaxf(v.x + b[col + 0], 0.f);
    v.y = fmaxf(v.y + b[col + 1], 0.f);
    v.z = fmaxf(v.z + b[col + 2], 0.f);
    v.w = fmaxf(v.w + b[col + 3], 0.f);
    ((float4*)out)[i] = v;
}

// ---------------- per-node head: p, q, voltage output ----------------
__global__ void k_node(const float* __restrict__ h2, const float* __restrict__ Wsw,
                       const float* __restrict__ Wv, const float* __restrict__ bv,
                       float* __restrict__ out_v, int nRows) {
    int n = blockIdx.x * (blockDim.x >> 5) + (threadIdx.x >> 5);
    if (n >= nRows) return;
    int l = threadIdx.x & 31;
    float a0 = h2[(size_t)n * 64 + l];
    float a1 = h2[(size_t)n * 64 + 32 + l];
    float pp = a0 * Wsw[l] + a1 * Wsw[32 + l];
    float qq = a0 * Wsw[64 + l] + a1 * Wsw[96 + l];
    float vv = a0 * Wv[l] + a1 * Wv[32 + l];
#pragma unroll
    for (int o = 16; o; o >>= 1) {
        pp += __shfl_xor_sync(0xffffffffu, pp, o);
        qq += __shfl_xor_sync(0xffffffffu, qq, o);
        vv += __shfl_xor_sync(0xffffffffu, vv, o);
    }
    if (l == 0) {
        g_p[n] = pp;
        g_q[n] = qq;
        float vr = 1.f / (1.f + expf(-(vv + bv[0])));
        float v = 0.9f + 0.2f * vr;
        float vw = v * v;
        vw = fminf(fmaxf(vw, 0.81f), 1.21f);
        out_v[n] = sqrtf(vw);
    }
}

// ---------------- per-edge head: sigmoid(p[src] + q[dst] + b) ----------------
__global__ void k_edge(const int* __restrict__ ei, int E,
                       const float* __restrict__ bsw, float* __restrict__ out) {
    int e = blockIdx.x * blockDim.x + threadIdx.x;
    if (e >= E) return;
    int s = ei[e];
    int d = ei[E + e];
    float z = g_p[s] + g_q[d] + bsw[0];
    float y = 1.f / (1.f + expf(-z));
    out[e] = fminf(fmaxf(y, 0.f), 1.f);
}

extern "C" void kernel_launch(void* const* d_in, const int* in_sizes, int n_in,
                              void* d_out, int out_size) {
    const float* x     = (const float*)d_in[0];
    const int*   ei    = (const int*)d_in[1];
    const float* W_enc = (const float*)d_in[2];
    const float* b_enc = (const float*)d_in[3];
    const float* W_g0  = (const float*)d_in[4];
    const float* b_g0  = (const float*)d_in[5];
    const float* W_g1  = (const float*)d_in[6];
    const float* b_g1  = (const float*)d_in[7];
    const float* W_sw  = (const float*)d_in[8];
    const float* b_sw  = (const float*)d_in[9];
    const float* W_v   = (const float*)d_in[10];
    const float* b_v   = (const float*)d_in[11];
    float* out = (float*)d_out;

    const int N = in_sizes[0] / 16;
    const int E = in_sizes[1] / 2;

    float *p_h, *p_hw, *p_agg;
    cudaGetSymbolAddress((void**)&p_h, g_h);
    cudaGetSymbolAddress((void**)&p_hw, g_hw);
    cudaGetSymbolAddress((void**)&p_agg, g_agg);

    // degrees
    k_zero_deg<<<(N + 255) / 256, 256>>>(N);
    k_count_deg<<<(E + 255) / 256, 256>>>(ei, E);
    k_dinv<<<(N + 255) / 256, 256>>>(N);

    // encoder
    k_encoder<<<(N + 15) / 16, 256>>>(x, W_enc, b_enc, p_h, N);

    // GCN layer 0
    k_sgemm<128, 8><<<(N + 127) / 128, 256>>>(p_h, W_g0, p_hw, N);
    k_init_self<<<(N * 128 / 4 + 255) / 256, 256>>>(p_hw, p_agg, N * 128, 128);
    k_scatter128<<<(E + 7) / 8, 256>>>(ei, E, p_hw, p_agg);
    k_finalize<<<(N * 128 / 4 + 255) / 256, 256>>>(p_agg, b_g0, p_agg, N * 128, 128);  // h1 in g_agg

    // GCN layer 1
    k_sgemm<64, 4><<<(N + 127) / 128, 256>>>(p_agg, W_g1, p_h, N);                      // hw1 in g_h
    k_init_self<<<(N * 64 / 4 + 255) / 256, 256>>>(p_h, p_hw, N * 64, 64);              // agg1 = g_hw
    k_scatter64<<<(E + 15) / 16, 256>>>(ei, E, p_h, p_hw);
    k_finalize<<<(N * 64 / 4 + 255) / 256, 256>>>(p_hw, b_g1, p_agg, N * 64, 64);       // h2 in g_agg

    // heads
    k_node<<<(N + 7) / 8, 256>>>(p_agg, W_sw, W_v, b_v, out + E, N);
    k_edge<<<(E + 255) / 256, 256>>>(ei, E, b_sw, out);
}

// round 3
// speedup vs baseline: 1.6721x; 1.6721x over previous
#include <cuda_runtime.h>
#include <cstdint>
#include <math.h>

#define MAXN 100000
#define MAXE 1600000
#define SCAN_BLK 1024

// ---- static scratch ----
__device__ float g_hw0[MAXN * 128];  // (relu(x Wenc)) @ Wg0
__device__ float g_h1 [MAXN * 128];  // relu(agg0 + b0)
__device__ float g_hw1[MAXN * 64];   // h1 @ Wg1
__device__ float g_dinv[MAXN];
__device__ int   g_deg [MAXN];
__device__ int   g_off [MAXN];       // exclusive CSR offsets (by dst)
__device__ int   g_cnt [MAXN];       // fill counters
__device__ int   g_col [MAXE];       // CSR column (src) ids
__device__ int   g_bsum[128];        // scan block sums
__device__ float g_p[MAXN];
__device__ float g_q[MAXN];

// ================= degree / CSR build =================
__global__ void k_zero(int n) {
    int i = blockIdx.x * blockDim.x + threadIdx.x;
    if (i < n) { g_deg[i] = 0; g_cnt[i] = 0; }
}

__global__ void k_count_deg(const int* __restrict__ ei, int E) {
    int e = blockIdx.x * blockDim.x + threadIdx.x;
    if (e >= E) return;
    atomicAdd(&g_deg[ei[E + e]], 1);
}

__global__ void k_scan1(int n) {
    __shared__ int sh[SCAN_BLK];
    int t = threadIdx.x;
    int i = blockIdx.x * SCAN_BLK + t;
    int v = (i < n) ? g_deg[i] : 0;
    sh[t] = v;
    __syncthreads();
#pragma unroll
    for (int o = 1; o < SCAN_BLK; o <<= 1) {
        int add = (t >= o) ? sh[t - o] : 0;
        __syncthreads();
        sh[t] += add;
        __syncthreads();
    }
    if (i < n) g_off[i] = sh[t] - v;  // exclusive
    if (t == SCAN_BLK - 1) g_bsum[blockIdx.x] = sh[t];
}

__global__ void k_scan2(int nb) {
    __shared__ int sh[128];
    int t = threadIdx.x;
    int v = (t < nb) ? g_bsum[t] : 0;
    sh[t] = v;
    __syncthreads();
#pragma unroll
    for (int o = 1; o < 128; o <<= 1) {
        int add = (t >= o) ? sh[t - o] : 0;
        __syncthreads();
        sh[t] += add;
        __syncthreads();
    }
    if (t < nb) g_bsum[t] = sh[t] - v;  // exclusive
}

__global__ void k_scan3(int n) {
    int i = blockIdx.x * blockDim.x + threadIdx.x;
    if (i < n) g_off[i] += g_bsum[i / SCAN_BLK];
}

__global__ void k_dinv(int n) {
    int i = blockIdx.x * blockDim.x + threadIdx.x;
    if (i < n) g_dinv[i] = rsqrtf((float)(g_deg[i] + 1));  // +1 self-loop
}

__global__ void k_fill(const int* __restrict__ ei, int E) {
    int e = blockIdx.x * blockDim.x + threadIdx.x;
    if (e >= E) return;
    int s = ei[e];
    int d = ei[E + e];
    int pos = g_off[d] + atomicAdd(&g_cnt[d], 1);
    g_col[pos] = s;
}

// ================= fused encoder + GEMM0 =================
// hw0[N,128] = (relu(x[N,16] @ Wenc[16,128] + benc)) @ Wg0[128,128]
__global__ void k_enc_gemm0(const float* __restrict__ x, const float* __restrict__ Wenc,
                            const float* __restrict__ benc, const float* __restrict__ Wg0,
                            float* __restrict__ C, int nRows) {
    constexpr int BM = 128, BN = 128, BK = 16, TM = 8, TN = 8;
    __shared__ float xst[16][128];   // x tile, transposed [k][row]
    __shared__ float We[16][128];    // Wenc [k][col]
    __shared__ float be[128];
    __shared__ float As[BK][BM];
    __shared__ float Bs[BK][BN];
    int tid = threadIdx.x;
    int rowBase = blockIdx.x * BM;

    // load Wenc + bias
    for (int i = tid; i < 16 * 128; i += 256) We[i / 128][i % 128] = Wenc[i];
    if (tid < 128) be[tid] = benc[tid];
    // load x tile (128 rows x 16), store transposed
#pragma unroll
    for (int i = 0; i < 2; ++i) {
        int idx = tid + i * 256;          // float4 slot
        int r = idx / 4, k4 = (idx % 4) * 4;
        int gr = rowBase + r;
        float4 v = make_float4(0.f, 0.f, 0.f, 0.f);
        if (gr < nRows) v = *(const float4*)(x + (size_t)gr * 16 + k4);
        xst[k4 + 0][r] = v.x; xst[k4 + 1][r] = v.y;
        xst[k4 + 2][r] = v.z; xst[k4 + 3][r] = v.w;
    }
    __syncthreads();

    int trow = tid / (BN / TN);
    int tcol = tid % (BN / TN);
    float acc[TM][TN];
#pragma unroll
    for (int i = 0; i < TM; ++i)
#pragma unroll
        for (int j = 0; j < TN; ++j) acc[i][j] = 0.f;

    for (int k0 = 0; k0 < 128; k0 += BK) {
        // compute A tile on the fly: As[kk][r] = relu(dot(x[r,:], Wenc[:,k0+kk]) + b)
#pragma unroll
        for (int i = 0; i < 8; ++i) {
            int idx = tid + i * 256;
            int kk = idx >> 7;     // uniform within warp
            int r = idx & 127;
            int col = k0 + kk;
            float a = be[col];
#pragma unroll
            for (int k = 0; k < 16; ++k) a += xst[k][r] * We[k][col];
            As[kk][r] = fmaxf(a, 0.f);
        }
        // load B tile
#pragma unroll
        for (int i = 0; i < 2; ++i) {
            int idx = tid + i * 256;
            int kk = idx / 32;
            int c = (idx % 32) * 4;
            *(float4*)&Bs[kk][c] = *(const float4*)(Wg0 + (size_t)(k0 + kk) * 128 + c);
        }
        __syncthreads();
#pragma unroll
        for (int k = 0; k < BK; ++k) {
            float ra[TM], rb[TN];
#pragma unroll
            for (int i = 0; i < TM; ++i) ra[i] = As[k][trow * TM + i];
#pragma unroll
            for (int j = 0; j < TN; ++j) rb[j] = Bs[k][tcol * TN + j];
#pragma unroll
            for (int i = 0; i < TM; ++i)
#pragma unroll
                for (int j = 0; j < TN; ++j) acc[i][j] += ra[i] * rb[j];
        }
        __syncthreads();
    }
#pragma unroll
    for (int i = 0; i < TM; ++i) {
        int gr = rowBase + trow * TM + i;
        if (gr < nRows) {
#pragma unroll
            for (int j = 0; j < TN; j += 4)
                *(float4*)(C + (size_t)gr * 128 + tcol * TN + j) =
                    make_float4(acc[i][j], acc[i][j + 1], acc[i][j + 2], acc[i][j + 3]);
        }
    }
}

// ================= SGEMM (layer 1): C[N,64] = A[N,128] @ W[128,64] =================
__global__ void k_sgemm64(const float* __restrict__ A, const float* __restrict__ W,
                          float* __restrict__ C, int nRows) {
    constexpr int BM = 128, BN = 64, BK = 16, TM = 8, TN = 4;
    __shared__ float As[BK][BM];
    __shared__ float Bs[BK][BN];
    int tid = threadIdx.x;
    int trow = tid / (BN / TN);
    int tcol = tid % (BN / TN);
    int rowBase = blockIdx.x * BM;
    float acc[TM][TN];
#pragma unroll
    for (int i = 0; i < TM; ++i)
#pragma unroll
        for (int j = 0; j < TN; ++j) acc[i][j] = 0.f;

    for (int k0 = 0; k0 < 128; k0 += BK) {
#pragma unroll
        for (int i = 0; i < 2; ++i) {
            int idx = tid + i * 256;
            int r = idx / 4;
            int kk = (idx % 4) * 4;
            float4 v = make_float4(0.f, 0.f, 0.f, 0.f);
            int gr = rowBase + r;
            if (gr < nRows) v = *(const float4*)(A + (size_t)gr * 128 + k0 + kk);
            As[kk + 0][r] = v.x; As[kk + 1][r] = v.y;
            As[kk + 2][r] = v.z; As[kk + 3][r] = v.w;
        }
        {
            int idx = tid;  // 16*64/4 = 256 float4
            int kk = idx / 16;
            int c = (idx % 16) * 4;
            *(float4*)&Bs[kk][c] = *(const float4*)(W + (size_t)(k0 + kk) * 64 + c);
        }
        __syncthreads();
#pragma unroll
        for (int k = 0; k < BK; ++k) {
            float ra[TM], rb[TN];
#pragma unroll
            for (int i = 0; i < TM; ++i) ra[i] = As[k][trow * TM + i];
#pragma unroll
            for (int j = 0; j < TN; ++j) rb[j] = Bs[k][tcol * TN + j];
#pragma unroll
            for (int i = 0; i < TM; ++i)
#pragma unroll
                for (int j = 0; j < TN; ++j) acc[i][j] += ra[i] * rb[j];
        }
        __syncthreads();
    }
#pragma unroll
    for (int i = 0; i < TM; ++i) {
        int gr = rowBase + trow * TM + i;
        if (gr < nRows)
            *(float4*)(C + (size_t)gr * 64 + tcol * TN) =
                make_float4(acc[i][0], acc[i][1], acc[i][2], acc[i][3]);
    }
}

// ================= gather aggregation, D=128: h1 = relu(agg(hw0) + b) =================
__global__ void k_agg128(const float* __restrict__ hw, const float* __restrict__ b,
                         float* __restrict__ outh, int nRows) {
    int n = blockIdx.x * (blockDim.x >> 5) + (threadIdx.x >> 5);
    if (n >= nRows) return;
    int lane = threadIdx.x & 31;
    float di = g_dinv[n];
    float4 acc = ((const float4*)(hw + (size_t)n * 128))[lane];
    float s2 = di * di;
    acc.x *= s2; acc.y *= s2; acc.z *= s2; acc.w *= s2;

    int beg = g_off[n];
    int end = beg + g_deg[n];
    int j = beg;
    for (; j + 2 <= end; j += 2) {
        int s0 = g_col[j], s1 = g_col[j + 1];
        float n0 = di * g_dinv[s0];
        float n1 = di * g_dinv[s1];
        float4 v0 = ((const float4*)(hw + (size_t)s0 * 128))[lane];
        float4 v1 = ((const float4*)(hw + (size_t)s1 * 128))[lane];
        acc.x += v0.x * n0 + v1.x * n1;
        acc.y += v0.y * n0 + v1.y * n1;
        acc.z += v0.z * n0 + v1.z * n1;
        acc.w += v0.w * n0 + v1.w * n1;
    }
    if (j < end) {
        int s0 = g_col[j];
        float n0 = di * g_dinv[s0];
        float4 v0 = ((const float4*)(hw + (size_t)s0 * 128))[lane];
        acc.x += v0.x * n0; acc.y += v0.y * n0;
        acc.z += v0.z * n0; acc.w += v0.w * n0;
    }
    const float4 bb = ((const float4*)b)[lane];
    acc.x = fmaxf(acc.x + bb.x, 0.f);
    acc.y = fmaxf(acc.y + bb.y, 0.f);
    acc.z = fmaxf(acc.z + bb.z, 0.f);
    acc.w = fmaxf(acc.w + bb.w, 0.f);
    ((float4*)(outh + (size_t)n * 128))[lane] = acc;
}

// ===== gather aggregation D=64 + fused head: h2 = relu(agg(hw1)+b); p,q,v =====
__global__ void k_agg64_head(const float* __restrict__ hw, const float* __restrict__ b,
                             const float* __restrict__ Wsw, const float* __restrict__ Wv,
                             const float* __restrict__ bv, float* __restrict__ out_v,
                             int nRows) {
    int n = blockIdx.x * (blockDim.x >> 5) + (threadIdx.x >> 5);
    if (n >= nRows) return;
    int lane = threadIdx.x & 31;
    float di = g_dinv[n];
    float2 acc = ((const float2*)(hw + (size_t)n * 64))[lane];
    float s2 = di * di;
    acc.x *= s2; acc.y *= s2;

    int beg = g_off[n];
    int end = beg + g_deg[n];
    int j = beg;
    for (; j + 2 <= end; j += 2) {
        int s0 = g_col[j], s1 = g_col[j + 1];
        float n0 = di * g_dinv[s0];
        float n1 = di * g_dinv[s1];
        float2 v0 = ((const float2*)(hw + (size_t)s0 * 64))[lane];
        float2 v1 = ((const float2*)(hw + (size_t)s1 * 64))[lane];
        acc.x += v0.x * n0 + v1.x * n1;
        acc.y += v0.y * n0 + v1.y * n1;
    }
    if (j < end) {
        int s0 = g_col[j];
        float n0 = di * g_dinv[s0];
        float2 v0 = ((const float2*)(hw + (size_t)s0 * 64))[lane];
        acc.x += v0.x * n0; acc.y += v0.y * n0;
    }
    int c = 2 * lane;
    float a0 = fmaxf(acc.x + b[c], 0.f);
    float a1 = fmaxf(acc.y + b[c + 1], 0.f);

    // head: p = h2 . Wsw[0:64], q = h2 . Wsw[64:128], v = h2 . Wv
    float pp = a0 * Wsw[c] + a1 * Wsw[c + 1];
    float qq = a0 * Wsw[64 + c] + a1 * Wsw[64 + c + 1];
    float vv = a0 * Wv[c] + a1 * Wv[c + 1];
#pragma unroll
    for (int o = 16; o; o >>= 1) {
        pp += __shfl_xor_sync(0xffffffffu, pp, o);
        qq += __shfl_xor_sync(0xffffffffu, qq, o);
        vv += __shfl_xor_sync(0xffffffffu, vv, o);
    }
    if (lane == 0) {
        g_p[n] = pp;
        g_q[n] = qq;
        float vr = 1.f / (1.f + expf(-(vv + bv[0])));
        float v = 0.9f + 0.2f * vr;
        float vw = fminf(fmaxf(v * v, 0.81f), 1.21f);
        out_v[n] = sqrtf(vw);
    }
}

// ================= per-edge head =================
__global__ void k_edge(const int* __restrict__ ei, int E,
                       const float* __restrict__ bsw, float* __restrict__ out) {
    int e = blockIdx.x * blockDim.x + threadIdx.x;
    if (e >= E) return;
    int s = ei[e];
    int d = ei[E + e];
    float z = g_p[s] + g_q[d] + bsw[0];
    float y = 1.f / (1.f + expf(-z));
    out[e] = fminf(fmaxf(y, 0.f), 1.f);
}

extern "C" void kernel_launch(void* const* d_in, const int* in_sizes, int n_in,
                              void* d_out, int out_size) {
    const float* x     = (const float*)d_in[0];
    const int*   ei    = (const int*)d_in[1];
    const float* W_enc = (const float*)d_in[2];
    const float* b_enc = (const float*)d_in[3];
    const float* W_g0  = (const float*)d_in[4];
    const float* b_g0  = (const float*)d_in[5];
    const float* W_g1  = (const float*)d_in[6];
    const float* b_g1  = (const float*)d_in[7];
    const float* W_sw  = (const float*)d_in[8];
    const float* b_sw  = (const float*)d_in[9];
    const float* W_v   = (const float*)d_in[10];
    const float* b_v   = (const float*)d_in[11];
    float* out = (float*)d_out;

    const int N = in_sizes[0] / 16;
    const int E = in_sizes[1] / 2;
    const int nScanBlocks = (N + SCAN_BLK - 1) / SCAN_BLK;

    float *p_hw0, *p_h1, *p_hw1;
    cudaGetSymbolAddress((void**)&p_hw0, g_hw0);
    cudaGetSymbolAddress((void**)&p_h1, g_h1);
    cudaGetSymbolAddress((void**)&p_hw1, g_hw1);

    // ---- CSR build ----
    k_zero<<<(N + 255) / 256, 256>>>(N);
    k_count_deg<<<(E + 255) / 256, 256>>>(ei, E);
    k_scan1<<<nScanBlocks, SCAN_BLK>>>(N);
    k_scan2<<<1, 128>>>(nScanBlocks);
    k_scan3<<<(N + 255) / 256, 256>>>(N);
    k_dinv<<<(N + 255) / 256, 256>>>(N);
    k_fill<<<(E + 255) / 256, 256>>>(ei, E);

    // ---- layer 0: fused encoder+GEMM, then gather-agg ----
    k_enc_gemm0<<<(N + 127) / 128, 256>>>(x, W_enc, b_enc, W_g0, p_hw0, N);
    k_agg128<<<(N + 7) / 8, 256>>>(p_hw0, b_g0, p_h1, N);

    // ---- layer 1: GEMM, then gather-agg + fused node head ----
    k_sgemm64<<<(N + 127) / 128, 256>>>(p_h1, W_g1, p_hw1, N);
    k_agg64_head<<<(N + 7) / 8, 256>>>(p_hw1, b_g1, W_sw, W_v, b_v, out + E, N);

    // ---- per-edge head ----
    k_edge<<<(E + 255) / 256, 256>>>(ei, E, b_sw, out);
}

// round 4
// speedup vs baseline: 1.8339x; 1.0968x over previous
#include <cuda_runtime.h>
#include <cstdint>
#include <math.h>

#define MAXN 100000
#define MAXE 1600000
#define SCAN_BLK 1024

// ---- static scratch ----
__device__ float g_hw0[MAXN * 128];
__device__ float g_h1 [MAXN * 128];
__device__ float g_hw1[MAXN * 64];
__device__ float g_dinv[MAXN];
__device__ int   g_deg [MAXN];
__device__ int   g_off [MAXN];
__device__ int   g_cnt [MAXN];
__device__ int   g_col [MAXE];
__device__ int   g_bsum[128];
__device__ float g_p[MAXN];
__device__ float g_q[MAXN];

__device__ __forceinline__ uint32_t f2tf32(float f) {
    uint32_t r;
    asm("cvt.rna.tf32.f32 %0, %1;" : "=r"(r) : "f"(f));
    return r;
}

__device__ __forceinline__ void mma_tf32(float c[4], const uint32_t a[4], const uint32_t b[2]) {
    asm volatile(
        "mma.sync.aligned.m16n8k8.row.col.f32.tf32.tf32.f32 "
        "{%0,%1,%2,%3}, {%4,%5,%6,%7}, {%8,%9}, {%0,%1,%2,%3};"
        : "+f"(c[0]), "+f"(c[1]), "+f"(c[2]), "+f"(c[3])
        : "r"(a[0]), "r"(a[1]), "r"(a[2]), "r"(a[3]), "r"(b[0]), "r"(b[1]));
}

// ================= degree / CSR build =================
__global__ void k_zero(int n) {
    int i = blockIdx.x * blockDim.x + threadIdx.x;
    if (i < n) { g_deg[i] = 0; g_cnt[i] = 0; }
}

__global__ void k_count_deg(const int* __restrict__ ei, int E) {
    int e = blockIdx.x * blockDim.x + threadIdx.x;
    if (e >= E) return;
    atomicAdd(&g_deg[ei[E + e]], 1);
}

__global__ void k_scan1(int n) {
    __shared__ int sh[SCAN_BLK];
    int t = threadIdx.x;
    int i = blockIdx.x * SCAN_BLK + t;
    int v = (i < n) ? g_deg[i] : 0;
    sh[t] = v;
    __syncthreads();
#pragma unroll
    for (int o = 1; o < SCAN_BLK; o <<= 1) {
        int add = (t >= o) ? sh[t - o] : 0;
        __syncthreads();
        sh[t] += add;
        __syncthreads();
    }
    if (i < n) g_off[i] = sh[t] - v;
    if (t == SCAN_BLK - 1) g_bsum[blockIdx.x] = sh[t];
}

__global__ void k_scan2(int nb) {
    __shared__ int sh[128];
    int t = threadIdx.x;
    int v = (t < nb) ? g_bsum[t] : 0;
    sh[t] = v;
    __syncthreads();
#pragma unroll
    for (int o = 1; o < 128; o <<= 1) {
        int add = (t >= o) ? sh[t - o] : 0;
        __syncthreads();
        sh[t] += add;
        __syncthreads();
    }
    if (t < nb) g_bsum[t] = sh[t] - v;
}

__global__ void k_scan3(int n) {
    int i = blockIdx.x * blockDim.x + threadIdx.x;
    if (i < n) g_off[i] += g_bsum[i / SCAN_BLK];
}

__global__ void k_dinv(int n) {
    int i = blockIdx.x * blockDim.x + threadIdx.x;
    if (i < n) g_dinv[i] = rsqrtf((float)(g_deg[i] + 1));
}

__global__ void k_fill(const int* __restrict__ ei, int E) {
    int e = blockIdx.x * blockDim.x + threadIdx.x;
    if (e >= E) return;
    int s = ei[e];
    int d = ei[E + e];
    int pos = g_off[d] + atomicAdd(&g_cnt[d], 1);
    g_col[pos] = s;
}

// ============ fused encoder + tf32 GEMM0: C[N,128] = relu(x Wenc + b) @ Wg0 ============
__global__ void k_enc_gemm0(const float* __restrict__ x, const float* __restrict__ Wenc,
                            const float* __restrict__ benc, const float* __restrict__ Wg0,
                            float* __restrict__ C, int nRows) {
    __shared__ float We[16][128];
    __shared__ float be[128];
    __shared__ uint32_t As[128 * 36];   // A chunk [128 rows][32 k], stride 36 (tf32 bits)
    __shared__ uint32_t Bs[128 * 36];   // W chunk [128 n][32 k], stride 36

    int tid = threadIdx.x;
    int lane = tid & 31;
    int wid = tid >> 5;
    int g = lane >> 2, t = lane & 3;
    int wr = wid & 3;        // warp row (32 rows)
    int wc = wid >> 2;       // warp col (64 cols)
    int rowBase = blockIdx.x * 128;

    // load Wenc + bias into smem
    for (int i = tid; i < 16 * 128; i += 256) We[i >> 7][i & 127] = Wenc[i];
    if (tid < 128) be[tid] = benc[tid];

    // x row in registers (two threads per row)
    int r = tid & 127;
    int half = tid >> 7;
    float xr[16];
    {
        int gr = rowBase + r;
#pragma unroll
        for (int i = 0; i < 4; ++i) {
            float4 v = make_float4(0.f, 0.f, 0.f, 0.f);
            if (gr < nRows) v = *(const float4*)(x + (size_t)gr * 16 + i * 4);
            xr[i * 4 + 0] = v.x; xr[i * 4 + 1] = v.y;
            xr[i * 4 + 2] = v.z; xr[i * 4 + 3] = v.w;
        }
    }
    __syncthreads();

    float acc[2][8][4];
#pragma unroll
    for (int ma = 0; ma < 2; ++ma)
#pragma unroll
        for (int na = 0; na < 8; ++na)
#pragma unroll
            for (int q = 0; q < 4; ++q) acc[ma][na][q] = 0.f;

    for (int k0 = 0; k0 < 128; k0 += 32) {
        // compute encoder chunk: As[r][lk] = relu(x[r,:] . Wenc[:, k0+lk] + b)
#pragma unroll
        for (int c = 0; c < 16; ++c) {
            int col = k0 + half * 16 + c;
            float a = be[col];
#pragma unroll
            for (int k = 0; k < 16; ++k) a += xr[k] * We[k][col];
            As[r * 36 + (half * 16 + c)] = f2tf32(fmaxf(a, 0.f));
        }
        // load W chunk transposed: Bs[n][lk] = Wg0[k0+lk][n]
#pragma unroll
        for (int i = 0; i < 16; ++i) {
            int idx = tid + i * 256;
            int kl = idx >> 7;
            int n = idx & 127;
            Bs[n * 36 + kl] = f2tf32(Wg0[(size_t)(k0 + kl) * 128 + n]);
        }
        __syncthreads();
#pragma unroll
        for (int ks = 0; ks < 4; ++ks) {
            int kb = ks * 8;
            uint32_t af[2][4];
#pragma unroll
            for (int ma = 0; ma < 2; ++ma) {
                int rr = wr * 32 + ma * 16 + g;
                af[ma][0] = As[rr * 36 + kb + t];
                af[ma][1] = As[(rr + 8) * 36 + kb + t];
                af[ma][2] = As[rr * 36 + kb + t + 4];
                af[ma][3] = As[(rr + 8) * 36 + kb + t + 4];
            }
#pragma unroll
            for (int na = 0; na < 8; ++na) {
                int n = wc * 64 + na * 8 + g;
                uint32_t bf[2];
                bf[0] = Bs[n * 36 + kb + t];
                bf[1] = Bs[n * 36 + kb + t + 4];
#pragma unroll
                for (int ma = 0; ma < 2; ++ma) mma_tf32(acc[ma][na], af[ma], bf);
            }
        }
        __syncthreads();
    }
    // epilogue
#pragma unroll
    for (int ma = 0; ma < 2; ++ma) {
        int r0 = rowBase + wr * 32 + ma * 16 + g;
#pragma unroll
        for (int na = 0; na < 8; ++na) {
            int col = wc * 64 + na * 8 + 2 * t;
            if (r0 < nRows)
                *(float2*)(C + (size_t)r0 * 128 + col) = make_float2(acc[ma][na][0], acc[ma][na][1]);
            if (r0 + 8 < nRows)
                *(float2*)(C + (size_t)(r0 + 8) * 128 + col) = make_float2(acc[ma][na][2], acc[ma][na][3]);
        }
    }
}

// ============ tf32 GEMM1: C[N,64] = A[N,128] @ W[128,64] ============
__global__ void k_gemm64(const float* __restrict__ A, const float* __restrict__ W,
                         float* __restrict__ C, int nRows) {
    __shared__ uint32_t As[128 * 36];
    __shared__ uint32_t Bs[64 * 36];

    int tid = threadIdx.x;
    int lane = tid & 31;
    int wid = tid >> 5;
    int g = lane >> 2, t = lane & 3;
    int wr = wid & 3;
    int wc = wid >> 2;   // 2 warp cols x 32
    int rowBase = blockIdx.x * 128;

    float acc[2][4][4];
#pragma unroll
    for (int ma = 0; ma < 2; ++ma)
#pragma unroll
        for (int na = 0; na < 4; ++na)
#pragma unroll
            for (int q = 0; q < 4; ++q) acc[ma][na][q] = 0.f;

    for (int k0 = 0; k0 < 128; k0 += 32) {
#pragma unroll
        for (int i = 0; i < 16; ++i) {
            int idx = tid + i * 256;
            int rr = idx >> 5;
            int kl = idx & 31;
            int gr = rowBase + rr;
            float v = (gr < nRows) ? A[(size_t)gr * 128 + k0 + kl] : 0.f;
            As[rr * 36 + kl] = f2tf32(v);
        }
#pragma unroll
        for (int i = 0; i < 8; ++i) {
            int idx = tid + i * 256;
            int kl = idx >> 6;
            int n = idx & 63;
            Bs[n * 36 + kl] = f2tf32(W[(size_t)(k0 + kl) * 64 + n]);
        }
        __syncthreads();
#pragma unroll
        for (int ks = 0; ks < 4; ++ks) {
            int kb = ks * 8;
            uint32_t af[2][4];
#pragma unroll
            for (int ma = 0; ma < 2; ++ma) {
                int rr = wr * 32 + ma * 16 + g;
                af[ma][0] = As[rr * 36 + kb + t];
                af[ma][1] = As[(rr + 8) * 36 + kb + t];
                af[ma][2] = As[rr * 36 + kb + t + 4];
                af[ma][3] = As[(rr + 8) * 36 + kb + t + 4];
            }
#pragma unroll
            for (int na = 0; na < 4; ++na) {
                int n = wc * 32 + na * 8 + g;
                uint32_t bf[2];
                bf[0] = Bs[n * 36 + kb + t];
                bf[1] = Bs[n * 36 + kb + t + 4];
#pragma unroll
                for (int ma = 0; ma < 2; ++ma) mma_tf32(acc[ma][na], af[ma], bf);
            }
        }
        __syncthreads();
    }
#pragma unroll
    for (int ma = 0; ma < 2; ++ma) {
        int r0 = rowBase + wr * 32 + ma * 16 + g;
#pragma unroll
        for (int na = 0; na < 4; ++na) {
            int col = wc * 32 + na * 8 + 2 * t;
            if (r0 < nRows)
                *(float2*)(C + (size_t)r0 * 64 + col) = make_float2(acc[ma][na][0], acc[ma][na][1]);
            if (r0 + 8 < nRows)
                *(float2*)(C + (size_t)(r0 + 8) * 64 + col) = make_float2(acc[ma][na][2], acc[ma][na][3]);
        }
    }
}

// ================= gather aggregation, D=128 =================
__global__ void k_agg128(const float* __restrict__ hw, const float* __restrict__ b,
                         float* __restrict__ outh, int nRows) {
    int n = blockIdx.x * (blockDim.x >> 5) + (threadIdx.x >> 5);
    if (n >= nRows) return;
    int lane = threadIdx.x & 31;
    float di = g_dinv[n];
    float4 acc = ((const float4*)(hw + (size_t)n * 128))[lane];
    float s2 = di * di;
    acc.x *= s2; acc.y *= s2; acc.z *= s2; acc.w *= s2;

    int beg = g_off[n];
    int end = beg + g_deg[n];
    for (int j0 = beg; j0 < end; j0 += 32) {
        int cnt = end - j0; if (cnt > 32) cnt = 32;
        int idx = 0; float dv = 0.f;
        if (lane < cnt) { idx = g_col[j0 + lane]; dv = g_dinv[idx] * di; }
        int jj = 0;
        for (; jj + 4 <= cnt; jj += 4) {
            int s0 = __shfl_sync(0xffffffffu, idx, jj);
            int s1 = __shfl_sync(0xffffffffu, idx, jj + 1);
            int s2i = __shfl_sync(0xffffffffu, idx, jj + 2);
            int s3 = __shfl_sync(0xffffffffu, idx, jj + 3);
            float w0 = __shfl_sync(0xffffffffu, dv, jj);
            float w1 = __shfl_sync(0xffffffffu, dv, jj + 1);
            float w2 = __shfl_sync(0xffffffffu, dv, jj + 2);
            float w3 = __shfl_sync(0xffffffffu, dv, jj + 3);
            float4 v0 = ((const float4*)(hw + (size_t)s0 * 128))[lane];
            float4 v1 = ((const float4*)(hw + (size_t)s1 * 128))[lane];
            float4 v2 = ((const float4*)(hw + (size_t)s2i * 128))[lane];
            float4 v3 = ((const float4*)(hw + (size_t)s3 * 128))[lane];
            acc.x += v0.x * w0 + v1.x * w1 + v2.x * w2 + v3.x * w3;
            acc.y += v0.y * w0 + v1.y * w1 + v2.y * w2 + v3.y * w3;
            acc.z += v0.z * w0 + v1.z * w1 + v2.z * w2 + v3.z * w3;
            acc.w += v0.w * w0 + v1.w * w1 + v2.w * w2 + v3.w * w3;
        }
        for (; jj < cnt; ++jj) {
            int s0 = __shfl_sync(0xffffffffu, idx, jj);
            float w0 = __shfl_sync(0xffffffffu, dv, jj);
            float4 v0 = ((const float4*)(hw + (size_t)s0 * 128))[lane];
            acc.x += v0.x * w0; acc.y += v0.y * w0;
            acc.z += v0.z * w0; acc.w += v0.w * w0;
        }
    }
    const float4 bb = ((const float4*)b)[lane];
    acc.x = fmaxf(acc.x + bb.x, 0.f);
    acc.y = fmaxf(acc.y + bb.y, 0.f);
    acc.z = fmaxf(acc.z + bb.z, 0.f);
    acc.w = fmaxf(acc.w + bb.w, 0.f);
    ((float4*)(outh + (size_t)n * 128))[lane] = acc;
}

// ===== gather aggregation D=64 + fused node head =====
__global__ void k_agg64_head(const float* __restrict__ hw, const float* __restrict__ b,
                             const float* __restrict__ Wsw, const float* __restrict__ Wv,
                             const float* __restrict__ bv, float* __restrict__ out_v,
                             int nRows) {
    int n = blockIdx.x * (blockDim.x >> 5) + (threadIdx.x >> 5);
    if (n >= nRows) return;
    int lane = threadIdx.x & 31;
    float di = g_dinv[n];
    float2 acc = ((const float2*)(hw + (size_t)n * 64))[lane];
    float s2 = di * di;
    acc.x *= s2; acc.y *= s2;

    int beg = g_off[n];
    int end = beg + g_deg[n];
    for (int j0 = beg; j0 < end; j0 += 32) {
        int cnt = end - j0; if (cnt > 32) cnt = 32;
        int idx = 0; float dv = 0.f;
        if (lane < cnt) { idx = g_col[j0 + lane]; dv = g_dinv[idx] * di; }
        int jj = 0;
        for (; jj + 4 <= cnt; jj += 4) {
            int s0 = __shfl_sync(0xffffffffu, idx, jj);
            int s1 = __shfl_sync(0xffffffffu, idx, jj + 1);
            int s2i = __shfl_sync(0xffffffffu, idx, jj + 2);
            int s3 = __shfl_sync(0xffffffffu, idx, jj + 3);
            float w0 = __shfl_sync(0xffffffffu, dv, jj);
            float w1 = __shfl_sync(0xffffffffu, dv, jj + 1);
            float w2 = __shfl_sync(0xffffffffu, dv, jj + 2);
            float w3 = __shfl_sync(0xffffffffu, dv, jj + 3);
            float2 v0 = ((const float2*)(hw + (size_t)s0 * 64))[lane];
            float2 v1 = ((const float2*)(hw + (size_t)s1 * 64))[lane];
            float2 v2 = ((const float2*)(hw + (size_t)s2i * 64))[lane];
            float2 v3 = ((const float2*)(hw + (size_t)s3 * 64))[lane];
            acc.x += v0.x * w0 + v1.x * w1 + v2.x * w2 + v3.x * w3;
            acc.y += v0.y * w0 + v1.y * w1 + v2.y * w2 + v3.y * w3;
        }
        for (; jj < cnt; ++jj) {
            int s0 = __shfl_sync(0xffffffffu, idx, jj);
            float w0 = __shfl_sync(0xffffffffu, dv, jj);
            float2 v0 = ((const float2*)(hw + (size_t)s0 * 64))[lane];
            acc.x += v0.x * w0; acc.y += v0.y * w0;
        }
    }
    int c = 2 * lane;
    float a0 = fmaxf(acc.x + b[c], 0.f);
    float a1 = fmaxf(acc.y + b[c + 1], 0.f);

    float pp = a0 * Wsw[c] + a1 * Wsw[c + 1];
    float qq = a0 * Wsw[64 + c] + a1 * Wsw[64 + c + 1];
    float vv = a0 * Wv[c] + a1 * Wv[c + 1];
#pragma unroll
    for (int o = 16; o; o >>= 1) {
        pp += __shfl_xor_sync(0xffffffffu, pp, o);
        qq += __shfl_xor_sync(0xffffffffu, qq, o);
        vv += __shfl_xor_sync(0xffffffffu, vv, o);
    }
    if (lane == 0) {
        g_p[n] = pp;
        g_q[n] = qq;
        float vr = 1.f / (1.f + expf(-(vv + bv[0])));
        float v = 0.9f + 0.2f * vr;
        float vw = fminf(fmaxf(v * v, 0.81f), 1.21f);
        out_v[n] = sqrtf(vw);
    }
}

// ================= per-edge head =================
__global__ void k_edge(const int* __restrict__ ei, int E,
                       const float* __restrict__ bsw, float* __restrict__ out) {
    int e = blockIdx.x * blockDim.x + threadIdx.x;
    if (e >= E) return;
    int s = ei[e];
    int d = ei[E + e];
    float z = g_p[s] + g_q[d] + bsw[0];
    float y = 1.f / (1.f + expf(-z));
    out[e] = fminf(fmaxf(y, 0.f), 1.f);
}

extern "C" void kernel_launch(void* const* d_in, const int* in_sizes, int n_in,
                              void* d_out, int out_size) {
    const float* x     = (const float*)d_in[0];
    const int*   ei    = (const int*)d_in[1];
    const float* W_enc = (const float*)d_in[2];
    const float* b_enc = (const float*)d_in[3];
    const float* W_g0  = (const float*)d_in[4];
    const float* b_g0  = (const float*)d_in[5];
    const float* W_g1  = (const float*)d_in[6];
    const float* b_g1  = (const float*)d_in[7];
    const float* W_sw  = (const float*)d_in[8];
    const float* b_sw  = (const float*)d_in[9];
    const float* W_v   = (const float*)d_in[10];
    const float* b_v   = (const float*)d_in[11];
    float* out = (float*)d_out;

    const int N = in_sizes[0] / 16;
    const int E = in_sizes[1] / 2;
    const int nScanBlocks = (N + SCAN_BLK - 1) / SCAN_BLK;

    float *p_hw0, *p_h1, *p_hw1;
    cudaGetSymbolAddress((void**)&p_hw0, g_hw0);
    cudaGetSymbolAddress((void**)&p_h1, g_h1);
    cudaGetSymbolAddress((void**)&p_hw1, g_hw1);

    // ---- CSR build ----
    k_zero<<<(N + 255) / 256, 256>>>(N);
    k_count_deg<<<(E + 255) / 256, 256>>>(ei, E);
    k_scan1<<<nScanBlocks, SCAN_BLK>>>(N);
    k_scan2<<<1, 128>>>(nScanBlocks);
    k_scan3<<<(N + 255) / 256, 256>>>(N);
    k_dinv<<<(N + 255) / 256, 256>>>(N);
    k_fill<<<(E + 255) / 256, 256>>>(ei, E);

    // ---- layer 0 ----
    k_enc_gemm0<<<(N + 127) / 128, 256>>>(x, W_enc, b_enc, W_g0, p_hw0, N);
    k_agg128<<<(N + 7) / 8, 256>>>(p_hw0, b_g0, p_h1, N);

    // ---- layer 1 ----
    k_gemm64<<<(N + 127) / 128, 256>>>(p_h1, W_g1, p_hw1, N);
    k_agg64_head<<<(N + 7) / 8, 256>>>(p_hw1, b_g1, W_sw, W_v, b_v, out + E, N);

    // ---- per-edge head ----
    k_edge<<<(E + 255) / 256, 256>>>(ei, E, b_sw, out);
}

// round 5
// speedup vs baseline: 2.0926x; 1.1411x over previous
#include <cuda_runtime.h>
#include <cuda_bf16.h>
#include <cstdint>
#include <math.h>

#define MAXN 100000
#define MAXE 1600000
#define SCAN_BLK 1024

// ---- static scratch ----
__device__ __nv_bfloat16 g_hw0[MAXN * 128];  // messages layer 0 (bf16)
__device__ float         g_h1 [MAXN * 128];  // relu(agg0 + b0), fp32
__device__ __nv_bfloat16 g_hw1[MAXN * 64];   // messages layer 1 (bf16)
__device__ float g_dinv[MAXN];
__device__ int   g_deg [MAXN];
__device__ int   g_off [MAXN];
__device__ int   g_cnt [MAXN];
__device__ int   g_col [MAXE];
__device__ int   g_bsum[128];
__device__ float g_p[MAXN];
__device__ float g_q[MAXN];

__device__ __forceinline__ uint32_t f2tf32(float f) {
    uint32_t r;
    asm("cvt.rna.tf32.f32 %0, %1;" : "=r"(r) : "f"(f));
    return r;
}

__device__ __forceinline__ void mma_tf32(float c[4], const uint32_t a[4], const uint32_t b[2]) {
    asm volatile(
        "mma.sync.aligned.m16n8k8.row.col.f32.tf32.tf32.f32 "
        "{%0,%1,%2,%3}, {%4,%5,%6,%7}, {%8,%9}, {%0,%1,%2,%3};"
        : "+f"(c[0]), "+f"(c[1]), "+f"(c[2]), "+f"(c[3])
        : "r"(a[0]), "r"(a[1]), "r"(a[2]), "r"(a[3]), "r"(b[0]), "r"(b[1]));
}

// ================= degree / CSR build =================
__global__ void k_zero(int n) {
    int i = blockIdx.x * blockDim.x + threadIdx.x;
    if (i < n) { g_deg[i] = 0; g_cnt[i] = 0; }
}

__global__ void k_count_deg(const int* __restrict__ ei, int E) {
    int e = blockIdx.x * blockDim.x + threadIdx.x;
    if (e >= E) return;
    atomicAdd(&g_deg[ei[E + e]], 1);
}

__global__ void k_scan1(int n) {
    __shared__ int sh[SCAN_BLK];
    int t = threadIdx.x;
    int i = blockIdx.x * SCAN_BLK + t;
    int v = (i < n) ? g_deg[i] : 0;
    sh[t] = v;
    __syncthreads();
#pragma unroll
    for (int o = 1; o < SCAN_BLK; o <<= 1) {
        int add = (t >= o) ? sh[t - o] : 0;
        __syncthreads();
        sh[t] += add;
        __syncthreads();
    }
    if (i < n) g_off[i] = sh[t] - v;
    if (t == SCAN_BLK - 1) g_bsum[blockIdx.x] = sh[t];
}

__global__ void k_scan2(int nb) {
    __shared__ int sh[128];
    int t = threadIdx.x;
    int v = (t < nb) ? g_bsum[t] : 0;
    sh[t] = v;
    __syncthreads();
#pragma unroll
    for (int o = 1; o < 128; o <<= 1) {
        int add = (t >= o) ? sh[t - o] : 0;
        __syncthreads();
        sh[t] += add;
        __syncthreads();
    }
    if (t < nb) g_bsum[t] = sh[t] - v;
}

__global__ void k_scan3(int n) {
    int i = blockIdx.x * blockDim.x + threadIdx.x;
    if (i < n) g_off[i] += g_bsum[i / SCAN_BLK];
}

__global__ void k_dinv(int n) {
    int i = blockIdx.x * blockDim.x + threadIdx.x;
    if (i < n) g_dinv[i] = rsqrtf((float)(g_deg[i] + 1));
}

__global__ void k_fill(const int* __restrict__ ei, int E) {
    int e = blockIdx.x * blockDim.x + threadIdx.x;
    if (e >= E) return;
    int s = ei[e];
    int d = ei[E + e];
    int pos = g_off[d] + atomicAdd(&g_cnt[d], 1);
    g_col[pos] = s;
}

// ============ fused encoder + tf32 GEMM0: hw0 = bf16(relu(x Wenc + b) @ Wg0) ============
__global__ void k_enc_gemm0(const float* __restrict__ x, const float* __restrict__ Wenc,
                            const float* __restrict__ benc, const float* __restrict__ Wg0,
                            __nv_bfloat16* __restrict__ C, int nRows) {
    __shared__ float We[16][128];
    __shared__ float be[128];
    __shared__ uint32_t As[128 * 36];
    __shared__ uint32_t Bs[128 * 36];

    int tid = threadIdx.x;
    int lane = tid & 31;
    int wid = tid >> 5;
    int g = lane >> 2, t = lane & 3;
    int wr = wid & 3;
    int wc = wid >> 2;
    int rowBase = blockIdx.x * 128;

    for (int i = tid; i < 16 * 128; i += 256) We[i >> 7][i & 127] = Wenc[i];
    if (tid < 128) be[tid] = benc[tid];

    int r = tid & 127;
    int half = tid >> 7;
    float xr[16];
    {
        int gr = rowBase + r;
#pragma unroll
        for (int i = 0; i < 4; ++i) {
            float4 v = make_float4(0.f, 0.f, 0.f, 0.f);
            if (gr < nRows) v = *(const float4*)(x + (size_t)gr * 16 + i * 4);
            xr[i * 4 + 0] = v.x; xr[i * 4 + 1] = v.y;
            xr[i * 4 + 2] = v.z; xr[i * 4 + 3] = v.w;
        }
    }
    __syncthreads();

    float acc[2][8][4];
#pragma unroll
    for (int ma = 0; ma < 2; ++ma)
#pragma unroll
        for (int na = 0; na < 8; ++na)
#pragma unroll
            for (int q = 0; q < 4; ++q) acc[ma][na][q] = 0.f;

    for (int k0 = 0; k0 < 128; k0 += 32) {
#pragma unroll
        for (int c = 0; c < 16; ++c) {
            int col = k0 + half * 16 + c;
            float a = be[col];
#pragma unroll
            for (int k = 0; k < 16; ++k) a += xr[k] * We[k][col];
            As[r * 36 + (half * 16 + c)] = f2tf32(fmaxf(a, 0.f));
        }
#pragma unroll
        for (int i = 0; i < 16; ++i) {
            int idx = tid + i * 256;
            int kl = idx >> 7;
            int n = idx & 127;
            Bs[n * 36 + kl] = f2tf32(Wg0[(size_t)(k0 + kl) * 128 + n]);
        }
        __syncthreads();
#pragma unroll
        for (int ks = 0; ks < 4; ++ks) {
            int kb = ks * 8;
            uint32_t af[2][4];
#pragma unroll
            for (int ma = 0; ma < 2; ++ma) {
                int rr = wr * 32 + ma * 16 + g;
                af[ma][0] = As[rr * 36 + kb + t];
                af[ma][1] = As[(rr + 8) * 36 + kb + t];
                af[ma][2] = As[rr * 36 + kb + t + 4];
                af[ma][3] = As[(rr + 8) * 36 + kb + t + 4];
            }
#pragma unroll
            for (int na = 0; na < 8; ++na) {
                int n = wc * 64 + na * 8 + g;
                uint32_t bf[2];
                bf[0] = Bs[n * 36 + kb + t];
                bf[1] = Bs[n * 36 + kb + t + 4];
#pragma unroll
                for (int ma = 0; ma < 2; ++ma) mma_tf32(acc[ma][na], af[ma], bf);
            }
        }
        __syncthreads();
    }
#pragma unroll
    for (int ma = 0; ma < 2; ++ma) {
        int r0 = rowBase + wr * 32 + ma * 16 + g;
#pragma unroll
        for (int na = 0; na < 8; ++na) {
            int col = wc * 64 + na * 8 + 2 * t;
            if (r0 < nRows)
                *(__nv_bfloat162*)(C + (size_t)r0 * 128 + col) =
                    __floats2bfloat162_rn(acc[ma][na][0], acc[ma][na][1]);
            if (r0 + 8 < nRows)
                *(__nv_bfloat162*)(C + (size_t)(r0 + 8) * 128 + col) =
                    __floats2bfloat162_rn(acc[ma][na][2], acc[ma][na][3]);
        }
    }
}

// ============ tf32 GEMM1: hw1 = bf16(A[N,128] @ W[128,64]) ============
__global__ void k_gemm64(const float* __restrict__ A, const float* __restrict__ W,
                         __nv_bfloat16* __restrict__ C, int nRows) {
    __shared__ uint32_t As[128 * 36];
    __shared__ uint32_t Bs[64 * 36];

    int tid = threadIdx.x;
    int lane = tid & 31;
    int wid = tid >> 5;
    int g = lane >> 2, t = lane & 3;
    int wr = wid & 3;
    int wc = wid >> 2;
    int rowBase = blockIdx.x * 128;

    float acc[2][4][4];
#pragma unroll
    for (int ma = 0; ma < 2; ++ma)
#pragma unroll
        for (int na = 0; na < 4; ++na)
#pragma unroll
            for (int q = 0; q < 4; ++q) acc[ma][na][q] = 0.f;

    for (int k0 = 0; k0 < 128; k0 += 32) {
#pragma unroll
        for (int i = 0; i < 16; ++i) {
            int idx = tid + i * 256;
            int rr = idx >> 5;
            int kl = idx & 31;
            int gr = rowBase + rr;
            float v = (gr < nRows) ? A[(size_t)gr * 128 + k0 + kl] : 0.f;
            As[rr * 36 + kl] = f2tf32(v);
        }
#pragma unroll
        for (int i = 0; i < 8; ++i) {
            int idx = tid + i * 256;
            int kl = idx >> 6;
            int n = idx & 63;
            Bs[n * 36 + kl] = f2tf32(W[(size_t)(k0 + kl) * 64 + n]);
        }
        __syncthreads();
#pragma unroll
        for (int ks = 0; ks < 4; ++ks) {
            int kb = ks * 8;
            uint32_t af[2][4];
#pragma unroll
            for (int ma = 0; ma < 2; ++ma) {
                int rr = wr * 32 + ma * 16 + g;
                af[ma][0] = As[rr * 36 + kb + t];
                af[ma][1] = As[(rr + 8) * 36 + kb + t];
                af[ma][2] = As[rr * 36 + kb + t + 4];
                af[ma][3] = As[(rr + 8) * 36 + kb + t + 4];
            }
#pragma unroll
            for (int na = 0; na < 4; ++na) {
                int n = wc * 32 + na * 8 + g;
                uint32_t bf[2];
                bf[0] = Bs[n * 36 + kb + t];
                bf[1] = Bs[n * 36 + kb + t + 4];
#pragma unroll
                for (int ma = 0; ma < 2; ++ma) mma_tf32(acc[ma][na], af[ma], bf);
            }
        }
        __syncthreads();
    }
#pragma unroll
    for (int ma = 0; ma < 2; ++ma) {
        int r0 = rowBase + wr * 32 + ma * 16 + g;
#pragma unroll
        for (int na = 0; na < 4; ++na) {
            int col = wc * 32 + na * 8 + 2 * t;
            if (r0 < nRows)
                *(__nv_bfloat162*)(C + (size_t)r0 * 64 + col) =
                    __floats2bfloat162_rn(acc[ma][na][0], acc[ma][na][1]);
            if (r0 + 8 < nRows)
                *(__nv_bfloat162*)(C + (size_t)(r0 + 8) * 64 + col) =
                    __floats2bfloat162_rn(acc[ma][na][2], acc[ma][na][3]);
        }
    }
}

__device__ __forceinline__ float4 ld_bf16x4(const __nv_bfloat16* base, int lane) {
    uint2 u = ((const uint2*)base)[lane];
    float2 f0 = __bfloat1622float2(*reinterpret_cast<__nv_bfloat162*>(&u.x));
    float2 f1 = __bfloat1622float2(*reinterpret_cast<__nv_bfloat162*>(&u.y));
    return make_float4(f0.x, f0.y, f1.x, f1.y);
}

// ================= gather aggregation, D=128 (bf16 messages) =================
__global__ void k_agg128(const __nv_bfloat16* __restrict__ hw, const float* __restrict__ b,
                         float* __restrict__ outh, int nRows) {
    int n = blockIdx.x * (blockDim.x >> 5) + (threadIdx.x >> 5);
    if (n >= nRows) return;
    int lane = threadIdx.x & 31;
    float di = g_dinv[n];
    float4 acc = ld_bf16x4(hw + (size_t)n * 128, lane);
    float s2 = di * di;
    acc.x *= s2; acc.y *= s2; acc.z *= s2; acc.w *= s2;

    int beg = g_off[n];
    int end = beg + g_deg[n];
    for (int j0 = beg; j0 < end; j0 += 32) {
        int cnt = end - j0; if (cnt > 32) cnt = 32;
        int idx = 0; float dv = 0.f;
        if (lane < cnt) { idx = g_col[j0 + lane]; dv = g_dinv[idx] * di; }
        int jj = 0;
        for (; jj + 4 <= cnt; jj += 4) {
            int s0 = __shfl_sync(0xffffffffu, idx, jj);
            int s1 = __shfl_sync(0xffffffffu, idx, jj + 1);
            int s2i = __shfl_sync(0xffffffffu, idx, jj + 2);
            int s3 = __shfl_sync(0xffffffffu, idx, jj + 3);
            float w0 = __shfl_sync(0xffffffffu, dv, jj);
            float w1 = __shfl_sync(0xffffffffu, dv, jj + 1);
            float w2 = __shfl_sync(0xffffffffu, dv, jj + 2);
            float w3 = __shfl_sync(0xffffffffu, dv, jj + 3);
            float4 v0 = ld_bf16x4(hw + (size_t)s0 * 128, lane);
            float4 v1 = ld_bf16x4(hw + (size_t)s1 * 128, lane);
            float4 v2 = ld_bf16x4(hw + (size_t)s2i * 128, lane);
            float4 v3 = ld_bf16x4(hw + (size_t)s3 * 128, lane);
            acc.x += v0.x * w0 + v1.x * w1 + v2.x * w2 + v3.x * w3;
            acc.y += v0.y * w0 + v1.y * w1 + v2.y * w2 + v3.y * w3;
            acc.z += v0.z * w0 + v1.z * w1 + v2.z * w2 + v3.z * w3;
            acc.w += v0.w * w0 + v1.w * w1 + v2.w * w2 + v3.w * w3;
        }
        for (; jj < cnt; ++jj) {
            int s0 = __shfl_sync(0xffffffffu, idx, jj);
            float w0 = __shfl_sync(0xffffffffu, dv, jj);
            float4 v0 = ld_bf16x4(hw + (size_t)s0 * 128, lane);
            acc.x += v0.x * w0; acc.y += v0.y * w0;
            acc.z += v0.z * w0; acc.w += v0.w * w0;
        }
    }
    const float4 bb = ((const float4*)b)[lane];
    acc.x = fmaxf(acc.x + bb.x, 0.f);
    acc.y = fmaxf(acc.y + bb.y, 0.f);
    acc.z = fmaxf(acc.z + bb.z, 0.f);
    acc.w = fmaxf(acc.w + bb.w, 0.f);
    ((float4*)(outh + (size_t)n * 128))[lane] = acc;
}

// ===== gather aggregation D=64 (bf16 messages) + fused node head =====
__global__ void k_agg64_head(const __nv_bfloat16* __restrict__ hw, const float* __restrict__ b,
                             const float* __restrict__ Wsw, const float* __restrict__ Wv,
                             const float* __restrict__ bv, float* __restrict__ out_v,
                             int nRows) {
    int n = blockIdx.x * (blockDim.x >> 5) + (threadIdx.x >> 5);
    if (n >= nRows) return;
    int lane = threadIdx.x & 31;
    float di = g_dinv[n];
    float2 acc;
    {
        uint32_t u = ((const uint32_t*)(hw + (size_t)n * 64))[lane];
        acc = __bfloat1622float2(*reinterpret_cast<__nv_bfloat162*>(&u));
    }
    float s2 = di * di;
    acc.x *= s2; acc.y *= s2;

    int beg = g_off[n];
    int end = beg + g_deg[n];
    for (int j0 = beg; j0 < end; j0 += 32) {
        int cnt = end - j0; if (cnt > 32) cnt = 32;
        int idx = 0; float dv = 0.f;
        if (lane < cnt) { idx = g_col[j0 + lane]; dv = g_dinv[idx] * di; }
        int jj = 0;
        for (; jj + 4 <= cnt; jj += 4) {
            int s0 = __shfl_sync(0xffffffffu, idx, jj);
            int s1 = __shfl_sync(0xffffffffu, idx, jj + 1);
            int s2i = __shfl_sync(0xffffffffu, idx, jj + 2);
            int s3 = __shfl_sync(0xffffffffu, idx, jj + 3);
            float w0 = __shfl_sync(0xffffffffu, dv, jj);
            float w1 = __shfl_sync(0xffffffffu, dv, jj + 1);
            float w2 = __shfl_sync(0xffffffffu, dv, jj + 2);
            float w3 = __shfl_sync(0xffffffffu, dv, jj + 3);
            uint32_t u0 = ((const uint32_t*)(hw + (size_t)s0 * 64))[lane];
            uint32_t u1 = ((const uint32_t*)(hw + (size_t)s1 * 64))[lane];
            uint32_t u2 = ((const uint32_t*)(hw + (size_t)s2i * 64))[lane];
            uint32_t u3 = ((const uint32_t*)(hw + (size_t)s3 * 64))[lane];
            float2 v0 = __bfloat1622float2(*reinterpret_cast<__nv_bfloat162*>(&u0));
            float2 v1 = __bfloat1622float2(*reinterpret_cast<__nv_bfloat162*>(&u1));
            float2 v2 = __bfloat1622float2(*reinterpret_cast<__nv_bfloat162*>(&u2));
            float2 v3 = __bfloat1622float2(*reinterpret_cast<__nv_bfloat162*>(&u3));
            acc.x += v0.x * w0 + v1.x * w1 + v2.x * w2 + v3.x * w3;
            acc.y += v0.y * w0 + v1.y * w1 + v2.y * w2 + v3.y * w3;
        }
        for (; jj < cnt; ++jj) {
            int s0 = __shfl_sync(0xffffffffu, idx, jj);
            float w0 = __shfl_sync(0xffffffffu, dv, jj);
            uint32_t u0 = ((const uint32_t*)(hw + (size_t)s0 * 64))[lane];
            float2 v0 = __bfloat1622float2(*reinterpret_cast<__nv_bfloat162*>(&u0));
            acc.x += v0.x * w0; acc.y += v0.y * w0;
        }
    }
    int c = 2 * lane;
    float a0 = fmaxf(acc.x + b[c], 0.f);
    float a1 = fmaxf(acc.y + b[c + 1], 0.f);

    float pp = a0 * Wsw[c] + a1 * Wsw[c + 1];
    float qq = a0 * Wsw[64 + c] + a1 * Wsw[64 + c + 1];
    float vv = a0 * Wv[c] + a1 * Wv[c + 1];
#pragma unroll
    for (int o = 16; o; o >>= 1) {
        pp += __shfl_xor_sync(0xffffffffu, pp, o);
        qq += __shfl_xor_sync(0xffffffffu, qq, o);
        vv += __shfl_xor_sync(0xffffffffu, vv, o);
    }
    if (lane == 0) {
        g_p[n] = pp;
        g_q[n] = qq;
        float vr = 1.f / (1.f + expf(-(vv + bv[0])));
        float v = 0.9f + 0.2f * vr;
        float vw = fminf(fmaxf(v * v, 0.81f), 1.21f);
        out_v[n] = sqrtf(vw);
    }
}

// ================= per-edge head =================
__global__ void k_edge(const int* __restrict__ ei, int E,
                       const float* __restrict__ bsw, float* __restrict__ out) {
    int e = blockIdx.x * blockDim.x + threadIdx.x;
    if (e >= E) return;
    int s = ei[e];
    int d = ei[E + e];
    float z = g_p[s] + g_q[d] + bsw[0];
    float y = 1.f / (1.f + expf(-z));
    out[e] = fminf(fmaxf(y, 0.f), 1.f);
}

extern "C" void kernel_launch(void* const* d_in, const int* in_sizes, int n_in,
                              void* d_out, int out_size) {
    const float* x     = (const float*)d_in[0];
    const int*   ei    = (const int*)d_in[1];
    const float* W_enc = (const float*)d_in[2];
    const float* b_enc = (const float*)d_in[3];
    const float* W_g0  = (const float*)d_in[4];
    const float* b_g0  = (const float*)d_in[5];
    const float* W_g1  = (const float*)d_in[6];
    const float* b_g1  = (const float*)d_in[7];
    const float* W_sw  = (const float*)d_in[8];
    const float* b_sw  = (const float*)d_in[9];
    const float* W_v   = (const float*)d_in[10];
    const float* b_v   = (const float*)d_in[11];
    float* out = (float*)d_out;

    const int N = in_sizes[0] / 16;
    const int E = in_sizes[1] / 2;
    const int nScanBlocks = (N + SCAN_BLK - 1) / SCAN_BLK;

    __nv_bfloat16 *p_hw0, *p_hw1;
    float* p_h1;
    cudaGetSymbolAddress((void**)&p_hw0, g_hw0);
    cudaGetSymbolAddress((void**)&p_h1, g_h1);
    cudaGetSymbolAddress((void**)&p_hw1, g_hw1);

    // ---- CSR build ----
    k_zero<<<(N + 255) / 256, 256>>>(N);
    k_count_deg<<<(E + 255) / 256, 256>>>(ei, E);
    k_scan1<<<nScanBlocks, SCAN_BLK>>>(N);
    k_scan2<<<1, 128>>>(nScanBlocks);
    k_scan3<<<(N + 255) / 256, 256>>>(N);
    k_dinv<<<(N + 255) / 256, 256>>>(N);
    k_fill<<<(E + 255) / 256, 256>>>(ei, E);

    // ---- layer 0 ----
    k_enc_gemm0<<<(N + 127) / 128, 256>>>(x, W_enc, b_enc, W_g0, p_hw0, N);
    k_agg128<<<(N + 7) / 8, 256>>>(p_hw0, b_g0, p_h1, N);

    // ---- layer 1 ----
    k_gemm64<<<(N + 127) / 128, 256>>>(p_h1, W_g1, p_hw1, N);
    k_agg64_head<<<(N + 7) / 8, 256>>>(p_hw1, b_g1, W_sw, W_v, b_v, out + E, N);

    // ---- per-edge head ----
    k_edge<<<(E + 255) / 256, 256>>>(ei, E, b_sw, out);
}

// round 6
// speedup vs baseline: 2.2756x; 1.0874x over previous
#include <cuda_runtime.h>
#include <cuda_bf16.h>
#include <cstdint>
#include <math.h>

#define MAXN 100000
#define MAXE 1600000
#define SCAN_BLK 1024

// ---- static scratch ----
__device__ __nv_bfloat16 g_hw0[MAXN * 128];  // messages layer 0 (bf16)
__device__ float         g_h1 [MAXN * 128];  // relu(agg0 + b0), fp32
__device__ __nv_bfloat16 g_hw1[MAXN * 64];   // messages layer 1 (bf16)
__device__ float g_dinv[MAXN];
__device__ int   g_deg [MAXN];
__device__ int   g_off [MAXN];
__device__ int   g_cnt [MAXN];
__device__ int   g_col [MAXE];
__device__ int   g_bsum[128];
__device__ float g_p[MAXN];
__device__ float g_q[MAXN];

__device__ __forceinline__ uint32_t f2tf32(float f) {
    uint32_t r;
    asm("cvt.rna.tf32.f32 %0, %1;" : "=r"(r) : "f"(f));
    return r;
}

__device__ __forceinline__ void mma_tf32(float c[4], const uint32_t a[4], const uint32_t b[2]) {
    asm volatile(
        "mma.sync.aligned.m16n8k8.row.col.f32.tf32.tf32.f32 "
        "{%0,%1,%2,%3}, {%4,%5,%6,%7}, {%8,%9}, {%0,%1,%2,%3};"
        : "+f"(c[0]), "+f"(c[1]), "+f"(c[2]), "+f"(c[3])
        : "r"(a[0]), "r"(a[1]), "r"(a[2]), "r"(a[3]), "r"(b[0]), "r"(b[1]));
}

// ================= degree / CSR build =================
__global__ void k_zero(int n) {
    int i = blockIdx.x * blockDim.x + threadIdx.x;
    if (i < n) g_deg[i] = 0;
}

__global__ void k_count_deg(const int* __restrict__ ei, int E) {
    int e = blockIdx.x * blockDim.x + threadIdx.x;
    if (e >= E) return;
    atomicAdd(&g_deg[ei[E + e]], 1);
}

__global__ void k_scan1(int n) {
    __shared__ int sh[SCAN_BLK];
    int t = threadIdx.x;
    int i = blockIdx.x * SCAN_BLK + t;
    int v = (i < n) ? g_deg[i] : 0;
    sh[t] = v;
    __syncthreads();
#pragma unroll
    for (int o = 1; o < SCAN_BLK; o <<= 1) {
        int add = (t >= o) ? sh[t - o] : 0;
        __syncthreads();
        sh[t] += add;
        __syncthreads();
    }
    if (i < n) g_off[i] = sh[t] - v;
    if (t == SCAN_BLK - 1) g_bsum[blockIdx.x] = sh[t];
}

__global__ void k_scan2(int nb) {
    __shared__ int sh[128];
    int t = threadIdx.x;
    int v = (t < nb) ? g_bsum[t] : 0;
    sh[t] = v;
    __syncthreads();
#pragma unroll
    for (int o = 1; o < 128; o <<= 1) {
        int add = (t >= o) ? sh[t - o] : 0;
        __syncthreads();
        sh[t] += add;
        __syncthreads();
    }
    if (t < nb) g_bsum[t] = sh[t] - v;
}

// scan fixup + cnt init + dinv, fused
__global__ void k_scan3(int n) {
    int i = blockIdx.x * blockDim.x + threadIdx.x;
    if (i >= n) return;
    int off = g_off[i] + g_bsum[i / SCAN_BLK];
    g_off[i] = off;
    g_cnt[i] = off;
    g_dinv[i] = rsqrtf((float)(g_deg[i] + 1));
}

__global__ void k_fill(const int* __restrict__ ei, int E) {
    int e = blockIdx.x * blockDim.x + threadIdx.x;
    if (e >= E) return;
    int s = ei[e];
    int d = ei[E + e];
    int pos = atomicAdd(&g_cnt[d], 1);
    g_col[pos] = s;
}

// ============ fused encoder + tf32 GEMM0: hw0 = bf16(relu(x Wenc + b) @ Wg0) ============
__global__ void k_enc_gemm0(const float* __restrict__ x, const float* __restrict__ Wenc,
                            const float* __restrict__ benc, const float* __restrict__ Wg0,
                            __nv_bfloat16* __restrict__ C, int nRows) {
    __shared__ float We[16][128];
    __shared__ float be[128];
    __shared__ uint32_t As[128 * 36];
    __shared__ uint32_t Bs[128 * 36];

    int tid = threadIdx.x;
    int lane = tid & 31;
    int wid = tid >> 5;
    int g = lane >> 2, t = lane & 3;
    int wr = wid & 3;
    int wc = wid >> 2;
    int rowBase = blockIdx.x * 128;

    for (int i = tid; i < 16 * 128; i += 256) We[i >> 7][i & 127] = Wenc[i];
    if (tid < 128) be[tid] = benc[tid];

    int r = tid & 127;
    int half = tid >> 7;
    float xr[16];
    {
        int gr = rowBase + r;
#pragma unroll
        for (int i = 0; i < 4; ++i) {
            float4 v = make_float4(0.f, 0.f, 0.f, 0.f);
            if (gr < nRows) v = *(const float4*)(x + (size_t)gr * 16 + i * 4);
            xr[i * 4 + 0] = v.x; xr[i * 4 + 1] = v.y;
            xr[i * 4 + 2] = v.z; xr[i * 4 + 3] = v.w;
        }
    }
    __syncthreads();

    float acc[2][8][4];
#pragma unroll
    for (int ma = 0; ma < 2; ++ma)
#pragma unroll
        for (int na = 0; na < 8; ++na)
#pragma unroll
            for (int q = 0; q < 4; ++q) acc[ma][na][q] = 0.f;

    for (int k0 = 0; k0 < 128; k0 += 32) {
#pragma unroll
        for (int c = 0; c < 16; ++c) {
            int col = k0 + half * 16 + c;
            float a = be[col];
#pragma unroll
            for (int k = 0; k < 16; ++k) a += xr[k] * We[k][col];
            As[r * 36 + (half * 16 + c)] = f2tf32(fmaxf(a, 0.f));
        }
#pragma unroll
        for (int i = 0; i < 16; ++i) {
            int idx = tid + i * 256;
            int kl = idx >> 7;
            int n = idx & 127;
            Bs[n * 36 + kl] = f2tf32(Wg0[(size_t)(k0 + kl) * 128 + n]);
        }
        __syncthreads();
#pragma unroll
        for (int ks = 0; ks < 4; ++ks) {
            int kb = ks * 8;
            uint32_t af[2][4];
#pragma unroll
            for (int ma = 0; ma < 2; ++ma) {
                int rr = wr * 32 + ma * 16 + g;
                af[ma][0] = As[rr * 36 + kb + t];
                af[ma][1] = As[(rr + 8) * 36 + kb + t];
                af[ma][2] = As[rr * 36 + kb + t + 4];
                af[ma][3] = As[(rr + 8) * 36 + kb + t + 4];
            }
#pragma unroll
            for (int na = 0; na < 8; ++na) {
                int n = wc * 64 + na * 8 + g;
                uint32_t bf[2];
                bf[0] = Bs[n * 36 + kb + t];
                bf[1] = Bs[n * 36 + kb + t + 4];
#pragma unroll
                for (int ma = 0; ma < 2; ++ma) mma_tf32(acc[ma][na], af[ma], bf);
            }
        }
        __syncthreads();
    }
#pragma unroll
    for (int ma = 0; ma < 2; ++ma) {
        int r0 = rowBase + wr * 32 + ma * 16 + g;
#pragma unroll
        for (int na = 0; na < 8; ++na) {
            int col = wc * 64 + na * 8 + 2 * t;
            if (r0 < nRows)
                *(__nv_bfloat162*)(C + (size_t)r0 * 128 + col) =
                    __floats2bfloat162_rn(acc[ma][na][0], acc[ma][na][1]);
            if (r0 + 8 < nRows)
                *(__nv_bfloat162*)(C + (size_t)(r0 + 8) * 128 + col) =
                    __floats2bfloat162_rn(acc[ma][na][2], acc[ma][na][3]);
        }
    }
}

// ============ tf32 GEMM1: hw1 = bf16(A[N,128] @ W[128,64]) ============
__global__ void k_gemm64(const float* __restrict__ A, const float* __restrict__ W,
                         __nv_bfloat16* __restrict__ C, int nRows) {
    __shared__ uint32_t As[128 * 36];
    __shared__ uint32_t Bs[64 * 36];

    int tid = threadIdx.x;
    int lane = tid & 31;
    int wid = tid >> 5;
    int g = lane >> 2, t = lane & 3;
    int wr = wid & 3;
    int wc = wid >> 2;
    int rowBase = blockIdx.x * 128;

    float acc[2][4][4];
#pragma unroll
    for (int ma = 0; ma < 2; ++ma)
#pragma unroll
        for (int na = 0; na < 4; ++na)
#pragma unroll
            for (int q = 0; q < 4; ++q) acc[ma][na][q] = 0.f;

    for (int k0 = 0; k0 < 128; k0 += 32) {
#pragma unroll
        for (int i = 0; i < 16; ++i) {
            int idx = tid + i * 256;
            int rr = idx >> 5;
            int kl = idx & 31;
            int gr = rowBase + rr;
            float v = (gr < nRows) ? A[(size_t)gr * 128 + k0 + kl] : 0.f;
            As[rr * 36 + kl] = f2tf32(v);
        }
#pragma unroll
        for (int i = 0; i < 8; ++i) {
            int idx = tid + i * 256;
            int kl = idx >> 6;
            int n = idx & 63;
            Bs[n * 36 + kl] = f2tf32(W[(size_t)(k0 + kl) * 64 + n]);
        }
        __syncthreads();
#pragma unroll
        for (int ks = 0; ks < 4; ++ks) {
            int kb = ks * 8;
            uint32_t af[2][4];
#pragma unroll
            for (int ma = 0; ma < 2; ++ma) {
                int rr = wr * 32 + ma * 16 + g;
                af[ma][0] = As[rr * 36 + kb + t];
                af[ma][1] = As[(rr + 8) * 36 + kb + t];
                af[ma][2] = As[rr * 36 + kb + t + 4];
                af[ma][3] = As[(rr + 8) * 36 + kb + t + 4];
            }
#pragma unroll
            for (int na = 0; na < 4; ++na) {
                int n = wc * 32 + na * 8 + g;
                uint32_t bf[2];
                bf[0] = Bs[n * 36 + kb + t];
                bf[1] = Bs[n * 36 + kb + t + 4];
#pragma unroll
                for (int ma = 0; ma < 2; ++ma) mma_tf32(acc[ma][na], af[ma], bf);
            }
        }
        __syncthreads();
    }
#pragma unroll
    for (int ma = 0; ma < 2; ++ma) {
        int r0 = rowBase + wr * 32 + ma * 16 + g;
#pragma unroll
        for (int na = 0; na < 4; ++na) {
            int col = wc * 32 + na * 8 + 2 * t;
            if (r0 < nRows)
                *(__nv_bfloat162*)(C + (size_t)r0 * 64 + col) =
                    __floats2bfloat162_rn(acc[ma][na][0], acc[ma][na][1]);
            if (r0 + 8 < nRows)
                *(__nv_bfloat162*)(C + (size_t)(r0 + 8) * 64 + col) =
                    __floats2bfloat162_rn(acc[ma][na][2], acc[ma][na][3]);
        }
    }
}

__device__ __forceinline__ float4 ld_bf16x4(const __nv_bfloat16* base, int lane) {
    uint2 u = ((const uint2*)base)[lane];
    float2 f0 = __bfloat1622float2(*reinterpret_cast<__nv_bfloat162*>(&u.x));
    float2 f1 = __bfloat1622float2(*reinterpret_cast<__nv_bfloat162*>(&u.y));
    return make_float4(f0.x, f0.y, f1.x, f1.y);
}

// ================= gather aggregation, D=128 (bf16 messages) =================
__global__ void k_agg128(const __nv_bfloat16* __restrict__ hw, const float* __restrict__ b,
                         float* __restrict__ outh, int nRows) {
    int n = blockIdx.x * (blockDim.x >> 5) + (threadIdx.x >> 5);
    if (n >= nRows) return;
    int lane = threadIdx.x & 31;
    float di = g_dinv[n];
    float4 acc = ld_bf16x4(hw + (size_t)n * 128, lane);
    float s2 = di * di;
    acc.x *= s2; acc.y *= s2; acc.z *= s2; acc.w *= s2;

    int beg = g_off[n];
    int end = beg + g_deg[n];
    for (int j0 = beg; j0 < end; j0 += 32) {
        int cnt = end - j0; if (cnt > 32) cnt = 32;
        int idx = 0; float dv = 0.f;
        if (lane < cnt) { idx = __ldg(&g_col[j0 + lane]); dv = g_dinv[idx] * di; }
        int jj = 0;
        for (; jj + 4 <= cnt; jj += 4) {
            int s0 = __shfl_sync(0xffffffffu, idx, jj);
            int s1 = __shfl_sync(0xffffffffu, idx, jj + 1);
            int s2i = __shfl_sync(0xffffffffu, idx, jj + 2);
            int s3 = __shfl_sync(0xffffffffu, idx, jj + 3);
            float w0 = __shfl_sync(0xffffffffu, dv, jj);
            float w1 = __shfl_sync(0xffffffffu, dv, jj + 1);
            float w2 = __shfl_sync(0xffffffffu, dv, jj + 2);
            float w3 = __shfl_sync(0xffffffffu, dv, jj + 3);
            float4 v0 = ld_bf16x4(hw + (size_t)s0 * 128, lane);
            float4 v1 = ld_bf16x4(hw + (size_t)s1 * 128, lane);
            float4 v2 = ld_bf16x4(hw + (size_t)s2i * 128, lane);
            float4 v3 = ld_bf16x4(hw + (size_t)s3 * 128, lane);
            acc.x += v0.x * w0 + v1.x * w1 + v2.x * w2 + v3.x * w3;
            acc.y += v0.y * w0 + v1.y * w1 + v2.y * w2 + v3.y * w3;
            acc.z += v0.z * w0 + v1.z * w1 + v2.z * w2 + v3.z * w3;
            acc.w += v0.w * w0 + v1.w * w1 + v2.w * w2 + v3.w * w3;
        }
        for (; jj < cnt; ++jj) {
            int s0 = __shfl_sync(0xffffffffu, idx, jj);
            float w0 = __shfl_sync(0xffffffffu, dv, jj);
            float4 v0 = ld_bf16x4(hw + (size_t)s0 * 128, lane);
            acc.x += v0.x * w0; acc.y += v0.y * w0;
            acc.z += v0.z * w0; acc.w += v0.w * w0;
        }
    }
    const float4 bb = ((const float4*)b)[lane];
    acc.x = fmaxf(acc.x + bb.x, 0.f);
    acc.y = fmaxf(acc.y + bb.y, 0.f);
    acc.z = fmaxf(acc.z + bb.z, 0.f);
    acc.w = fmaxf(acc.w + bb.w, 0.f);
    ((float4*)(outh + (size_t)n * 128))[lane] = acc;
}

// ===== gather aggregation D=64 (bf16 messages) + fused node head =====
__global__ void k_agg64_head(const __nv_bfloat16* __restrict__ hw, const float* __restrict__ b,
                             const float* __restrict__ Wsw, const float* __restrict__ Wv,
                             const float* __restrict__ bv, float* __restrict__ out_v,
                             int nRows) {
    int n = blockIdx.x * (blockDim.x >> 5) + (threadIdx.x >> 5);
    if (n >= nRows) return;
    int lane = threadIdx.x & 31;
    float di = g_dinv[n];
    float2 acc;
    {
        uint32_t u = ((const uint32_t*)(hw + (size_t)n * 64))[lane];
        acc = __bfloat1622float2(*reinterpret_cast<__nv_bfloat162*>(&u));
    }
    float s2 = di * di;
    acc.x *= s2; acc.y *= s2;

    int beg = g_off[n];
    int end = beg + g_deg[n];
    for (int j0 = beg; j0 < end; j0 += 32) {
        int cnt = end - j0; if (cnt > 32) cnt = 32;
        int idx = 0; float dv = 0.f;
        if (lane < cnt) { idx = __ldg(&g_col[j0 + lane]); dv = g_dinv[idx] * di; }
        int jj = 0;
        for (; jj + 4 <= cnt; jj += 4) {
            int s0 = __shfl_sync(0xffffffffu, idx, jj);
            int s1 = __shfl_sync(0xffffffffu, idx, jj + 1);
            int s2i = __shfl_sync(0xffffffffu, idx, jj + 2);
            int s3 = __shfl_sync(0xffffffffu, idx, jj + 3);
            float w0 = __shfl_sync(0xffffffffu, dv, jj);
            float w1 = __shfl_sync(0xffffffffu, dv, jj + 1);
            float w2 = __shfl_sync(0xffffffffu, dv, jj + 2);
            float w3 = __shfl_sync(0xffffffffu, dv, jj + 3);
            uint32_t u0 = ((const uint32_t*)(hw + (size_t)s0 * 64))[lane];
            uint32_t u1 = ((const uint32_t*)(hw + (size_t)s1 * 64))[lane];
            uint32_t u2 = ((const uint32_t*)(hw + (size_t)s2i * 64))[lane];
            uint32_t u3 = ((const uint32_t*)(hw + (size_t)s3 * 64))[lane];
            float2 v0 = __bfloat1622float2(*reinterpret_cast<__nv_bfloat162*>(&u0));
            float2 v1 = __bfloat1622float2(*reinterpret_cast<__nv_bfloat162*>(&u1));
            float2 v2 = __bfloat1622float2(*reinterpret_cast<__nv_bfloat162*>(&u2));
            float2 v3 = __bfloat1622float2(*reinterpret_cast<__nv_bfloat162*>(&u3));
            acc.x += v0.x * w0 + v1.x * w1 + v2.x * w2 + v3.x * w3;
            acc.y += v0.y * w0 + v1.y * w1 + v2.y * w2 + v3.y * w3;
        }
        for (; jj < cnt; ++jj) {
            int s0 = __shfl_sync(0xffffffffu, idx, jj);
            float w0 = __shfl_sync(0xffffffffu, dv, jj);
            uint32_t u0 = ((const uint32_t*)(hw + (size_t)s0 * 64))[lane];
            float2 v0 = __bfloat1622float2(*reinterpret_cast<__nv_bfloat162*>(&u0));
            acc.x += v0.x * w0; acc.y += v0.y * w0;
        }
    }
    int c = 2 * lane;
    float a0 = fmaxf(acc.x + b[c], 0.f);
    float a1 = fmaxf(acc.y + b[c + 1], 0.f);

    float pp = a0 * Wsw[c] + a1 * Wsw[c + 1];
    float qq = a0 * Wsw[64 + c] + a1 * Wsw[64 + c + 1];
    float vv = a0 * Wv[c] + a1 * Wv[c + 1];
#pragma unroll
    for (int o = 16; o; o >>= 1) {
        pp += __shfl_xor_sync(0xffffffffu, pp, o);
        qq += __shfl_xor_sync(0xffffffffu, qq, o);
        vv += __shfl_xor_sync(0xffffffffu, vv, o);
    }
    if (lane == 0) {
        g_p[n] = pp;
        g_q[n] = qq;
        float vr = 1.f / (1.f + expf(-(vv + bv[0])));
        float v = 0.9f + 0.2f * vr;
        float vw = fminf(fmaxf(v * v, 0.81f), 1.21f);
        out_v[n] = sqrtf(vw);
    }
}

// ================= per-edge head =================
__global__ void k_edge(const int* __restrict__ ei, int E,
                       const float* __restrict__ bsw, float* __restrict__ out) {
    int e = blockIdx.x * blockDim.x + threadIdx.x;
    if (e >= E) return;
    int s = ei[e];
    int d = ei[E + e];
    float z = __ldg(&g_p[s]) + __ldg(&g_q[d]) + bsw[0];
    float y = 1.f / (1.f + expf(-z));
    out[e] = fminf(fmaxf(y, 0.f), 1.f);
}

extern "C" void kernel_launch(void* const* d_in, const int* in_sizes, int n_in,
                              void* d_out, int out_size) {
    const float* x     = (const float*)d_in[0];
    const int*   ei    = (const int*)d_in[1];
    const float* W_enc = (const float*)d_in[2];
    const float* b_enc = (const float*)d_in[3];
    const float* W_g0  = (const float*)d_in[4];
    const float* b_g0  = (const float*)d_in[5];
    const float* W_g1  = (const float*)d_in[6];
    const float* b_g1  = (const float*)d_in[7];
    const float* W_sw  = (const float*)d_in[8];
    const float* b_sw  = (const float*)d_in[9];
    const float* W_v   = (const float*)d_in[10];
    const float* b_v   = (const float*)d_in[11];
    float* out = (float*)d_out;

    const int N = in_sizes[0] / 16;
    const int E = in_sizes[1] / 2;
    const int nScanBlocks = (N + SCAN_BLK - 1) / SCAN_BLK;

    __nv_bfloat16 *p_hw0, *p_hw1;
    float* p_h1;
    cudaGetSymbolAddress((void**)&p_hw0, g_hw0);
    cudaGetSymbolAddress((void**)&p_h1, g_h1);
    cudaGetSymbolAddress((void**)&p_hw1, g_hw1);

    // One-time resources (created on the uncaptured correctness call; reused
    // by the capture call — deterministic, no work is skipped).
    static cudaStream_t s_side = nullptr;
    static cudaEvent_t s_fork = nullptr, s_join = nullptr;
    if (s_side == nullptr) {
        cudaStreamCreateWithFlags(&s_side, cudaStreamNonBlocking);
        cudaEventCreateWithFlags(&s_fork, cudaEventDisableTiming);
        cudaEventCreateWithFlags(&s_join, cudaEventDisableTiming);
    }

    // ---- fork: CSR build on side stream, encoder+GEMM0 on main stream ----
    cudaEventRecord(s_fork, 0);
    cudaStreamWaitEvent(s_side, s_fork, 0);

    k_zero     <<<(N + 255) / 256, 256, 0, s_side>>>(N);
    k_count_deg<<<(E + 255) / 256, 256, 0, s_side>>>(ei, E);
    k_scan1    <<<nScanBlocks, SCAN_BLK, 0, s_side>>>(N);
    k_scan2    <<<1, 128, 0, s_side>>>(nScanBlocks);
    k_scan3    <<<(N + 255) / 256, 256, 0, s_side>>>(N);
    k_fill     <<<(E + 255) / 256, 256, 0, s_side>>>(ei, E);
    cudaEventRecord(s_join, s_side);

    k_enc_gemm0<<<(N + 127) / 128, 256>>>(x, W_enc, b_enc, W_g0, p_hw0, N);

    // ---- join ----
    cudaStreamWaitEvent(0, s_join, 0);

    // ---- layer 0 aggregation ----
    k_agg128<<<(N + 7) / 8, 256>>>(p_hw0, b_g0, p_h1, N);

    // ---- layer 1 ----
    k_gemm64<<<(N + 127) / 128, 256>>>(p_h1, W_g1, p_hw1, N);
    k_agg64_head<<<(N + 7) / 8, 256>>>(p_hw1, b_g1, W_sw, W_v, b_v, out + E, N);

    // ---- per-edge head ----
    k_edge<<<(E + 255) / 256, 256>>>(ei, E, b_sw, out);
}